// round 7
// baseline (speedup 1.0000x reference)
#include <cuda_runtime.h>
#include <cstdint>

// ---------------------------------------------------------------------------
// SubGraph: 3x (MLP -> gather/scatter-max -> concat) -> cluster max-pool ->
// column-wise L2 normalization.
// N=50000, E=800000, C0=64, H=64, NC=2500. Channels 64->128->256->512.
// Round 7: round-4 proven stream topology (CSR build overlap only) +
//          round-5 MLP core (128x64 tile, 4x8 microtile, fused head+tail).
// ---------------------------------------------------------------------------

// Static scratch (no allocations allowed)
__device__ __align__(16) float g_X1[50000 * 128];
__device__ __align__(16) float g_X2[50000 * 256];
__device__ __align__(16) float g_X3[50000 * 512];
__device__ __align__(16) float g_pool[2500 * 512];

__device__ int g_cnt[50000];
__device__ int g_off[50001];
__device__ int g_cur[50000];
__device__ int g_csr[800000];

__device__ int g_ccnt[2500];
__device__ int g_coff[2501];
__device__ int g_ccur[2500];
__device__ int g_ccsr[50000];

__device__ __forceinline__ float4 max4(float4 a, float4 b) {
    return make_float4(fmaxf(a.x, b.x), fmaxf(a.y, b.y),
                       fmaxf(a.z, b.z), fmaxf(a.w, b.w));
}

// ---------------------------------------------------------------------------
// CSR build
// ---------------------------------------------------------------------------
__global__ void hist_kernel(const int* __restrict__ idx, int* __restrict__ cnt, int m)
{
    int i = blockIdx.x * blockDim.x + threadIdx.x;
    if (i < m) atomicAdd(&cnt[__ldg(idx + i)], 1);
}

__global__ void scan_kernel(const int* __restrict__ cnt, int* __restrict__ off,
                            int* __restrict__ cur, int n)
{
    __shared__ int sums[1024];
    int tid = threadIdx.x;
    int chunk = (n + 1023) >> 10;
    int start = tid * chunk;
    int lim = min(start + chunk, n);
    int s = 0;
    for (int i = start; i < lim; ++i) s += cnt[i];
    sums[tid] = s;
    __syncthreads();
    for (int d = 1; d < 1024; d <<= 1) {
        int v = (tid >= d) ? sums[tid - d] : 0;
        __syncthreads();
        sums[tid] += v;
        __syncthreads();
    }
    int run = (tid == 0) ? 0 : sums[tid - 1];
    for (int i = start; i < lim; ++i) {
        off[i] = run; cur[i] = run;
        run += cnt[i];
    }
    if (tid == 1023) off[n] = sums[1023];
}

__global__ void fill_edge_kernel(const int* __restrict__ src, const int* __restrict__ dst,
                                 int* __restrict__ cur, int* __restrict__ csr, int E)
{
    int e = blockIdx.x * blockDim.x + threadIdx.x;
    if (e >= E) return;
    int pos = atomicAdd(&cur[__ldg(dst + e)], 1);
    csr[pos] = __ldg(src + e);
}

__global__ void fill_node_kernel(const int* __restrict__ cl, int* __restrict__ ccur,
                                 int* __restrict__ ccsr, int n)
{
    int i = blockIdx.x * blockDim.x + threadIdx.x;
    if (i >= n) return;
    int pos = atomicAdd(&ccur[__ldg(cl + i)], 1);
    ccsr[pos] = i;
}

// ---------------------------------------------------------------------------
// Fused MLP: Y[:, :C_OUT] = relu(X[:, :C_IN] @ w1 + b1) @ w2 + b2
// Y row stride = 2*C_OUT (aggr half written by agg kernel).
// Tile 128 rows x 64 cols, 256 threads, 4x8 microtile.
// tx = tid&7 (8 col-groups of 8), ty = tid>>3 (32 row-groups of 4).
// xs: transposed input chunk [64 k][128 r], aliased later as ts[k][r].
// ---------------------------------------------------------------------------
template<int C_IN, int C_OUT>
__global__ void __launch_bounds__(256, 3) mlp_kernel(
    const float* __restrict__ X,
    const float* __restrict__ w1, const float* __restrict__ b1,
    const float* __restrict__ w2, const float* __restrict__ b2,
    float* __restrict__ Y, int n)
{
    constexpr int LD_IN  = (C_IN == 64) ? 64 : C_IN;   // layer0 input has no concat
    constexpr int LD_OUT = 2 * C_OUT;

    __shared__ float ws[64 * 64];
    __shared__ float xs[64 * 128];      // input chunk; later aliased as ts[k][r]
    float* ts = xs;

    const int tid = threadIdx.x;
    const int tx = tid & 7, ty = tid >> 3;
    const int r0 = ty * 4, j0 = tx * 8;
    const int rowBase = blockIdx.x * 128;

    // ---- matmul1: acc[r][j] = X_tile @ w1, K-chunked by 64 ----
    float acc[4][8] = {};
#pragma unroll
    for (int kc = 0; kc < C_IN / 64; ++kc) {
        for (int i = tid; i < 128 * 16; i += 256) {
            int r = i & 127, kv = i >> 7;
            int row = rowBase + r;
            float4 v = make_float4(0.f, 0.f, 0.f, 0.f);
            if (row < n) v = *(const float4*)&X[(long)row * LD_IN + kc * 64 + kv * 4];
            xs[(kv * 4 + 0) * 128 + r] = v.x;
            xs[(kv * 4 + 1) * 128 + r] = v.y;
            xs[(kv * 4 + 2) * 128 + r] = v.z;
            xs[(kv * 4 + 3) * 128 + r] = v.w;
        }
        const float4* w1c = (const float4*)(w1 + (long)kc * 64 * 64);
        for (int i = tid; i < 1024; i += 256)
            ((float4*)ws)[i] = w1c[i];
        __syncthreads();

#pragma unroll 4
        for (int k = 0; k < 64; ++k) {
            float4 av = *(const float4*)(xs + k * 128 + r0);
            float4 b0 = *(const float4*)(ws + k * 64 + j0);
            float4 b1v = *(const float4*)(ws + k * 64 + j0 + 4);
            float ar[4] = {av.x, av.y, av.z, av.w};
            float br[8] = {b0.x, b0.y, b0.z, b0.w, b1v.x, b1v.y, b1v.z, b1v.w};
#pragma unroll
            for (int i = 0; i < 4; ++i)
#pragma unroll
                for (int j = 0; j < 8; ++j)
                    acc[i][j] += ar[i] * br[j];
        }
        __syncthreads();
    }

    // ---- bias + relu, store t transposed ts[k][r] ----
    float4 bb0 = __ldg((const float4*)&b1[j0]);
    float4 bb1 = __ldg((const float4*)&b1[j0 + 4]);
    float bb[8] = {bb0.x, bb0.y, bb0.z, bb0.w, bb1.x, bb1.y, bb1.z, bb1.w};
#pragma unroll
    for (int i = 0; i < 4; ++i)
#pragma unroll
        for (int j = 0; j < 8; ++j)
            acc[i][j] = fmaxf(acc[i][j] + bb[j], 0.f);
#pragma unroll
    for (int jj = 0; jj < 8; ++jj)
        *(float4*)&ts[(j0 + jj) * 128 + r0] =
            make_float4(acc[0][jj], acc[1][jj], acc[2][jj], acc[3][jj]);
    __syncthreads();

    // ---- matmul2: Y = t @ w2 + b2, in 64-col slices ----
#pragma unroll
    for (int cc = 0; cc < C_OUT / 64; ++cc) {
        for (int i = tid; i < 1024; i += 256) {
            int k = i >> 4, jv = i & 15;
            *(float4*)&ws[k * 64 + jv * 4] =
                __ldg((const float4*)&w2[(long)k * C_OUT + cc * 64 + jv * 4]);
        }
        __syncthreads();

        float a2[4][8] = {};
#pragma unroll 4
        for (int k = 0; k < 64; ++k) {
            float4 av = *(const float4*)(ts + k * 128 + r0);
            float4 b0 = *(const float4*)(ws + k * 64 + j0);
            float4 b1v = *(const float4*)(ws + k * 64 + j0 + 4);
            float ar[4] = {av.x, av.y, av.z, av.w};
            float br[8] = {b0.x, b0.y, b0.z, b0.w, b1v.x, b1v.y, b1v.z, b1v.w};
#pragma unroll
            for (int i = 0; i < 4; ++i)
#pragma unroll
                for (int j = 0; j < 8; ++j)
                    a2[i][j] += ar[i] * br[j];
        }
        __syncthreads();

        int col = cc * 64 + j0;
        float4 c0 = __ldg((const float4*)&b2[col]);
        float4 c1 = __ldg((const float4*)&b2[col + 4]);
#pragma unroll
        for (int i = 0; i < 4; ++i) {
            int row = rowBase + r0 + i;
            if (row < n) {
                *(float4*)&Y[(long)row * LD_OUT + col] =
                    make_float4(a2[i][0] + c0.x, a2[i][1] + c0.y, a2[i][2] + c0.z, a2[i][3] + c0.w);
                *(float4*)&Y[(long)row * LD_OUT + col + 4] =
                    make_float4(a2[i][4] + c1.x, a2[i][5] + c1.y, a2[i][6] + c1.z, a2[i][7] + c1.w);
            }
        }
    }
}

// ---------------------------------------------------------------------------
// CSR gather-max aggregation: aggr[node] = max over in-edges of h[src]; 0 if none.
// ---------------------------------------------------------------------------
template<int C>
__global__ void __launch_bounds__(256) agg_kernel(
    float* __restrict__ Xn,
    const int* __restrict__ csr, const int* __restrict__ off, int n)
{
    constexpr int LD  = 2 * C;
    constexpr int V   = C / 4;
    constexpr int LPE = (V < 32) ? V : 32;
    constexpr int EPW = 32 / LPE;
    constexpr int NV  = V / LPE;

    int gwarp = (int)((blockIdx.x * 256u + threadIdx.x) >> 5);
    int lane  = threadIdx.x & 31;
    int node  = gwarp * EPW + (EPW > 1 ? lane / LPE : 0);
    if (node >= n) return;
    int li = lane % LPE;

    int beg = off[node], end = off[node + 1];

    float4 m[NV];
#pragma unroll
    for (int v = 0; v < NV; ++v)
        m[v] = make_float4(-INFINITY, -INFINITY, -INFINITY, -INFINITY);

    int e = beg;
    for (; e + 3 < end; e += 4) {
        int s0 = __ldg(csr + e), s1 = __ldg(csr + e + 1);
        int s2 = __ldg(csr + e + 2), s3 = __ldg(csr + e + 3);
        const float4* h0 = (const float4*)(Xn + (long)s0 * LD) + li;
        const float4* h1 = (const float4*)(Xn + (long)s1 * LD) + li;
        const float4* h2 = (const float4*)(Xn + (long)s2 * LD) + li;
        const float4* h3 = (const float4*)(Xn + (long)s3 * LD) + li;
#pragma unroll
        for (int v = 0; v < NV; ++v) {
            float4 a = h0[v * LPE];
            float4 b = h1[v * LPE];
            float4 c = h2[v * LPE];
            float4 d = h3[v * LPE];
            m[v] = max4(m[v], max4(max4(a, b), max4(c, d)));
        }
    }
    for (; e < end; ++e) {
        const float4* h0 = (const float4*)(Xn + (long)__ldg(csr + e) * LD) + li;
#pragma unroll
        for (int v = 0; v < NV; ++v)
            m[v] = max4(m[v], h0[v * LPE]);
    }

    float4* ap = (float4*)(Xn + (long)node * LD + C);
    if (beg == end) {
#pragma unroll
        for (int v = 0; v < NV; ++v)
            ap[li + v * LPE] = make_float4(0.f, 0.f, 0.f, 0.f);
    } else {
#pragma unroll
        for (int v = 0; v < NV; ++v)
            ap[li + v * LPE] = m[v];
    }
}

// ---------------------------------------------------------------------------
// Cluster max-pool via CSR
// ---------------------------------------------------------------------------
__global__ void __launch_bounds__(128) pool_kernel(
    const float* __restrict__ X3, const int* __restrict__ ccsr,
    const int* __restrict__ coff, float* __restrict__ pool)
{
    int c = blockIdx.x;
    int t = threadIdx.x;
    int beg = coff[c], end = coff[c + 1];

    float4 m = make_float4(-INFINITY, -INFINITY, -INFINITY, -INFINITY);
    int i = beg;
    for (; i + 3 < end; i += 4) {
        float4 a = ((const float4*)(X3 + (long)ccsr[i] * 512))[t];
        float4 b = ((const float4*)(X3 + (long)ccsr[i + 1] * 512))[t];
        float4 c2 = ((const float4*)(X3 + (long)ccsr[i + 2] * 512))[t];
        float4 d = ((const float4*)(X3 + (long)ccsr[i + 3] * 512))[t];
        m = max4(m, max4(max4(a, b), max4(c2, d)));
    }
    for (; i < end; ++i)
        m = max4(m, ((const float4*)(X3 + (long)ccsr[i] * 512))[t]);
    if (beg == end) m = make_float4(0.f, 0.f, 0.f, 0.f);
    ((float4*)(pool + (long)c * 512))[t] = m;
}

// Column-wise normalize, coalesced
__global__ void __launch_bounds__(256) normalize_kernel(
    const float* __restrict__ pool, float* __restrict__ out, int nc)
{
    int lane  = threadIdx.x & 31;
    int phase = threadIdx.x >> 5;
    int col   = blockIdx.x * 32 + lane;

    float ss = 0.f;
    for (int r = phase; r < nc; r += 8) {
        float v = pool[(long)r * 512 + col];
        ss += v * v;
    }
    __shared__ float red[256];
    red[threadIdx.x] = ss;
    __syncthreads();
#pragma unroll
    for (int s = 128; s >= 32; s >>= 1) {
        if (threadIdx.x < s) red[threadIdx.x] += red[threadIdx.x + s];
        __syncthreads();
    }
    if (threadIdx.x < 32) red[threadIdx.x] = 1.0f / (sqrtf(red[threadIdx.x]) + 1e-6f);
    __syncthreads();
    float inv = red[lane];
    for (int r = phase; r < nc; r += 8)
        out[(long)r * 512 + col] = pool[(long)r * 512 + col] * inv;
}

// ---------------------------------------------------------------------------
extern "C" void kernel_launch(void* const* d_in, const int* in_sizes, int n_in,
                              void* d_out, int out_size)
{
    const float* x   = (const float*)d_in[0];
    const int*   ei  = (const int*)d_in[1];
    const int*   cl  = (const int*)d_in[2];
    const float *w1_0 = (const float*)d_in[3],  *b1_0 = (const float*)d_in[4];
    const float *w2_0 = (const float*)d_in[5],  *b2_0 = (const float*)d_in[6];
    const float *w1_1 = (const float*)d_in[7],  *b1_1 = (const float*)d_in[8];
    const float *w2_1 = (const float*)d_in[9],  *b2_1 = (const float*)d_in[10];
    const float *w1_2 = (const float*)d_in[11], *b1_2 = (const float*)d_in[12];
    const float *w2_2 = (const float*)d_in[13], *b2_2 = (const float*)d_in[14];

    int n  = in_sizes[0] / 64;
    int E  = in_sizes[1] / 2;
    int nc = out_size / 512;
    const int* src = ei;
    const int* dst = ei + E;

    float* X1;   cudaGetSymbolAddress((void**)&X1, g_X1);
    float* X2;   cudaGetSymbolAddress((void**)&X2, g_X2);
    float* X3;   cudaGetSymbolAddress((void**)&X3, g_X3);
    float* pool; cudaGetSymbolAddress((void**)&pool, g_pool);
    int *cnt, *off, *cur, *csr, *ccnt, *coff, *ccur, *ccsr;
    cudaGetSymbolAddress((void**)&cnt,  g_cnt);
    cudaGetSymbolAddress((void**)&off,  g_off);
    cudaGetSymbolAddress((void**)&cur,  g_cur);
    cudaGetSymbolAddress((void**)&csr,  g_csr);
    cudaGetSymbolAddress((void**)&ccnt, g_ccnt);
    cudaGetSymbolAddress((void**)&coff, g_coff);
    cudaGetSymbolAddress((void**)&ccur, g_ccur);
    cudaGetSymbolAddress((void**)&ccsr, g_ccsr);

    // Round-4-proven topology: one side stream, two events.
    static cudaStream_t s2 = nullptr;
    static cudaEvent_t evFork = nullptr, evCsr = nullptr;
    if (!s2) {
        cudaStreamCreateWithFlags(&s2, cudaStreamNonBlocking);
        cudaEventCreateWithFlags(&evFork, cudaEventDisableTiming);
        cudaEventCreateWithFlags(&evCsr,  cudaEventDisableTiming);
    }

    // ---- CSR build on side stream (overlaps mlp layer 0) ----
    cudaEventRecord(evFork, 0);
    cudaStreamWaitEvent(s2, evFork, 0);
    cudaMemsetAsync(cnt,  0, (size_t)n  * sizeof(int), s2);
    cudaMemsetAsync(ccnt, 0, (size_t)nc * sizeof(int), s2);
    hist_kernel<<<(E + 255) / 256, 256, 0, s2>>>(dst, cnt, E);
    hist_kernel<<<(n + 255) / 256, 256, 0, s2>>>(cl, ccnt, n);
    scan_kernel<<<1, 1024, 0, s2>>>(cnt, off, cur, n);
    scan_kernel<<<1, 1024, 0, s2>>>(ccnt, coff, ccur, nc);
    fill_edge_kernel<<<(E + 255) / 256, 256, 0, s2>>>(src, dst, cur, csr, E);
    fill_node_kernel<<<(n + 255) / 256, 256, 0, s2>>>(cl, ccur, ccsr, n);
    cudaEventRecord(evCsr, s2);

    int nb = (n + 127) / 128;

    // ---- Layer 0: 64 -> 64 (no concat on input) ----
    mlp_kernel<64, 64><<<nb, 256>>>(x, w1_0, b1_0, w2_0, b2_0, X1, n);
    cudaStreamWaitEvent(0, evCsr, 0);
    agg_kernel<64><<<((n + 1) / 2 * 32 + 255) / 256, 256>>>(X1, csr, off, n);

    // ---- Layer 1: 128 -> 128 ----
    mlp_kernel<128, 128><<<nb, 256>>>(X1, w1_1, b1_1, w2_1, b2_1, X2, n);
    agg_kernel<128><<<(n * 32 + 255) / 256, 256>>>(X2, csr, off, n);

    // ---- Layer 2: 256 -> 256 ----
    mlp_kernel<256, 256><<<nb, 256>>>(X2, w1_2, b1_2, w2_2, b2_2, X3, n);
    agg_kernel<256><<<(n * 32 + 255) / 256, 256>>>(X3, csr, off, n);

    // ---- Cluster pool + normalize ----
    pool_kernel<<<nc, 128>>>(X3, ccsr, coff, pool);
    normalize_kernel<<<16, 256>>>(pool, (float*)d_out, nc);
}

// round 8
// speedup vs baseline: 1.1337x; 1.1337x over previous
#include <cuda_runtime.h>
#include <cstdint>

// ---------------------------------------------------------------------------
// SubGraph: 3x (MLP -> gather/scatter-max -> concat) -> cluster max-pool ->
// column-wise L2 normalization.
// N=50000, E=800000, C0=64, H=64, NC=2500. Channels 64->128->256->512.
// Round 8: round-4 MLP geometry (64x64 tile, 4x4 microtile, 33KB smem, occ 4)
//          split into head (h-half of matmul1, overlaps agg on side stream)
//          and tail (aggr-half + relu + matmul2). CSR build overlapped.
// ---------------------------------------------------------------------------

// Static scratch (no allocations allowed)
__device__ __align__(16) float g_X1[50000 * 128];
__device__ __align__(16) float g_X2[50000 * 256];
__device__ __align__(16) float g_X3[50000 * 512];
__device__ __align__(16) float g_pool[2500 * 512];
__device__ __align__(16) float g_tp[50000 * 64];   // partial t (head output)

__device__ int g_cnt[50000];
__device__ int g_off[50001];
__device__ int g_cur[50000];
__device__ int g_csr[800000];

__device__ int g_ccnt[2500];
__device__ int g_coff[2501];
__device__ int g_ccur[2500];
__device__ int g_ccsr[50000];

__device__ __forceinline__ float4 max4(float4 a, float4 b) {
    return make_float4(fmaxf(a.x, b.x), fmaxf(a.y, b.y),
                       fmaxf(a.z, b.z), fmaxf(a.w, b.w));
}

// ---------------------------------------------------------------------------
// CSR build
// ---------------------------------------------------------------------------
__global__ void hist_kernel(const int* __restrict__ idx, int* __restrict__ cnt, int m)
{
    int i = blockIdx.x * blockDim.x + threadIdx.x;
    if (i < m) atomicAdd(&cnt[__ldg(idx + i)], 1);
}

__global__ void scan_kernel(const int* __restrict__ cnt, int* __restrict__ off,
                            int* __restrict__ cur, int n)
{
    __shared__ int sums[1024];
    int tid = threadIdx.x;
    int chunk = (n + 1023) >> 10;
    int start = tid * chunk;
    int lim = min(start + chunk, n);
    int s = 0;
    for (int i = start; i < lim; ++i) s += cnt[i];
    sums[tid] = s;
    __syncthreads();
    for (int d = 1; d < 1024; d <<= 1) {
        int v = (tid >= d) ? sums[tid - d] : 0;
        __syncthreads();
        sums[tid] += v;
        __syncthreads();
    }
    int run = (tid == 0) ? 0 : sums[tid - 1];
    for (int i = start; i < lim; ++i) {
        off[i] = run; cur[i] = run;
        run += cnt[i];
    }
    if (tid == 1023) off[n] = sums[1023];
}

__global__ void fill_edge_kernel(const int* __restrict__ src, const int* __restrict__ dst,
                                 int* __restrict__ cur, int* __restrict__ csr, int E)
{
    int e = blockIdx.x * blockDim.x + threadIdx.x;
    if (e >= E) return;
    int pos = atomicAdd(&cur[__ldg(dst + e)], 1);
    csr[pos] = __ldg(src + e);
}

__global__ void fill_node_kernel(const int* __restrict__ cl, int* __restrict__ ccur,
                                 int* __restrict__ ccsr, int n)
{
    int i = blockIdx.x * blockDim.x + threadIdx.x;
    if (i >= n) return;
    int pos = atomicAdd(&ccur[__ldg(cl + i)], 1);
    ccsr[pos] = i;
}

// ---------------------------------------------------------------------------
// MLP blocks, round-4 geometry: 64-row tile, 256 threads (16x16), 4x4 microtile.
// tx=tid&15 (16 col-groups of 4), ty=tid>>4 (16 row-groups of 4).
// xs transposed chunk [64 k][64 r]; ws weight chunk [64 k][64 n]; ts [64 r][68].
// ---------------------------------------------------------------------------

// head: tp[row][0:64] = X[:, KOFF:KOFF+KLEN] @ w1[KOFF:KOFF+KLEN, :]
template<int LD_IN, int KOFF, int KLEN>
__global__ void __launch_bounds__(256, 4) mlp_head(
    const float* __restrict__ X, const float* __restrict__ w1,
    float* __restrict__ tp, int n)
{
    __shared__ float ws[64 * 64];
    __shared__ float xs[64 * 64];

    const int tid = threadIdx.x;
    const int tx = tid & 15, ty = tid >> 4;
    const int r0 = ty * 4, j0 = tx * 4;
    const int rowBase = blockIdx.x * 64;

    float acc[4][4] = {};
#pragma unroll
    for (int kc = 0; kc < KLEN / 64; ++kc) {
        for (int i = tid; i < 64 * 16; i += 256) {
            int r = i & 63, kv = i >> 6;
            int row = rowBase + r;
            float4 v = make_float4(0.f, 0.f, 0.f, 0.f);
            if (row < n) v = *(const float4*)&X[(long)row * LD_IN + KOFF + kc * 64 + kv * 4];
            xs[(kv * 4 + 0) * 64 + r] = v.x;
            xs[(kv * 4 + 1) * 64 + r] = v.y;
            xs[(kv * 4 + 2) * 64 + r] = v.z;
            xs[(kv * 4 + 3) * 64 + r] = v.w;
        }
        const float4* w1c = (const float4*)(w1 + (long)(KOFF + kc * 64) * 64);
        for (int i = tid; i < 1024; i += 256)
            ((float4*)ws)[i] = w1c[i];
        __syncthreads();

#pragma unroll 4
        for (int k = 0; k < 64; ++k) {
            float4 xv = *(const float4*)(xs + k * 64 + r0);
            float4 wv = *(const float4*)(ws + k * 64 + j0);
            float xr[4] = {xv.x, xv.y, xv.z, xv.w};
            float wr[4] = {wv.x, wv.y, wv.z, wv.w};
#pragma unroll
            for (int i = 0; i < 4; ++i)
#pragma unroll
                for (int j = 0; j < 4; ++j)
                    acc[i][j] += xr[i] * wr[j];
        }
        __syncthreads();
    }

#pragma unroll
    for (int i = 0; i < 4; ++i) {
        int row = rowBase + r0 + i;
        if (row < n)
            *(float4*)&tp[(long)row * 64 + j0] =
                make_float4(acc[i][0], acc[i][1], acc[i][2], acc[i][3]);
    }
}

// tail: acc = (tp?) + X[:, KOFF:KOFF+KLEN] @ w1[KOFF:]; t = relu(acc+b1);
//       Y[:, :C_OUT] = t @ w2 + b2   (Y row stride = 2*C_OUT)
template<int LD_IN, int C_OUT, int KOFF, int KLEN, bool HAS_TP>
__global__ void __launch_bounds__(256, 4) mlp_tail(
    const float* __restrict__ X, const float* __restrict__ tp,
    const float* __restrict__ w1, const float* __restrict__ b1,
    const float* __restrict__ w2, const float* __restrict__ b2,
    float* __restrict__ Y, int n)
{
    constexpr int LD_OUT = 2 * C_OUT;
    constexpr int TSL = 68;

    __shared__ float ws[64 * 64];
    __shared__ float buf[64 * TSL];   // xs [64k][64r] chunk, aliased by ts [64r][68]
    float* xs = buf;
    float* ts = buf;

    const int tid = threadIdx.x;
    const int tx = tid & 15, ty = tid >> 4;
    const int r0 = ty * 4, j0 = tx * 4;
    const int rowBase = blockIdx.x * 64;

    float acc[4][4];
    if (HAS_TP) {
#pragma unroll
        for (int i = 0; i < 4; ++i) {
            int row = rowBase + r0 + i;
            float4 p = make_float4(0.f, 0.f, 0.f, 0.f);
            if (row < n) p = *(const float4*)&tp[(long)row * 64 + j0];
            acc[i][0] = p.x; acc[i][1] = p.y; acc[i][2] = p.z; acc[i][3] = p.w;
        }
    } else {
#pragma unroll
        for (int i = 0; i < 4; ++i)
#pragma unroll
            for (int j = 0; j < 4; ++j)
                acc[i][j] = 0.f;
    }

    // ---- matmul1 remainder over [KOFF, KOFF+KLEN) ----
#pragma unroll
    for (int kc = 0; kc < KLEN / 64; ++kc) {
        for (int i = tid; i < 64 * 16; i += 256) {
            int r = i & 63, kv = i >> 6;
            int row = rowBase + r;
            float4 v = make_float4(0.f, 0.f, 0.f, 0.f);
            if (row < n) v = *(const float4*)&X[(long)row * LD_IN + KOFF + kc * 64 + kv * 4];
            xs[(kv * 4 + 0) * 64 + r] = v.x;
            xs[(kv * 4 + 1) * 64 + r] = v.y;
            xs[(kv * 4 + 2) * 64 + r] = v.z;
            xs[(kv * 4 + 3) * 64 + r] = v.w;
        }
        const float4* w1c = (const float4*)(w1 + (long)(KOFF + kc * 64) * 64);
        for (int i = tid; i < 1024; i += 256)
            ((float4*)ws)[i] = w1c[i];
        __syncthreads();

#pragma unroll 4
        for (int k = 0; k < 64; ++k) {
            float4 xv = *(const float4*)(xs + k * 64 + r0);
            float4 wv = *(const float4*)(ws + k * 64 + j0);
            float xr[4] = {xv.x, xv.y, xv.z, xv.w};
            float wr[4] = {wv.x, wv.y, wv.z, wv.w};
#pragma unroll
            for (int i = 0; i < 4; ++i)
#pragma unroll
                for (int j = 0; j < 4; ++j)
                    acc[i][j] += xr[i] * wr[j];
        }
        __syncthreads();
    }

    // ---- bias + relu -> ts [r][68] ----
    float4 bb1 = __ldg((const float4*)&b1[j0]);
    float bba[4] = {bb1.x, bb1.y, bb1.z, bb1.w};
#pragma unroll
    for (int i = 0; i < 4; ++i) {
        float4 o;
        o.x = fmaxf(acc[i][0] + bba[0], 0.f);
        o.y = fmaxf(acc[i][1] + bba[1], 0.f);
        o.z = fmaxf(acc[i][2] + bba[2], 0.f);
        o.w = fmaxf(acc[i][3] + bba[3], 0.f);
        *(float4*)&ts[(r0 + i) * TSL + j0] = o;
    }

    // ---- matmul2: Y = t @ w2 + b2, 64-col output slices ----
#pragma unroll
    for (int cc = 0; cc < C_OUT / 64; ++cc) {
        __syncthreads();
        for (int i = tid; i < 64 * 16; i += 256) {
            int k = i >> 4, jv = i & 15;
            ((float4*)ws)[i] = __ldg((const float4*)&w2[(long)k * C_OUT + cc * 64 + jv * 4]);
        }
        __syncthreads();

        float a2[4][4] = {};
#pragma unroll
        for (int k4 = 0; k4 < 64; k4 += 4) {
            float4 t0 = *(const float4*)&ts[(r0 + 0) * TSL + k4];
            float4 t1 = *(const float4*)&ts[(r0 + 1) * TSL + k4];
            float4 t2 = *(const float4*)&ts[(r0 + 2) * TSL + k4];
            float4 t3 = *(const float4*)&ts[(r0 + 3) * TSL + k4];
            float4 w0 = *(const float4*)&ws[(k4 + 0) * 64 + j0];
            float4 w1v = *(const float4*)&ws[(k4 + 1) * 64 + j0];
            float4 w2v = *(const float4*)&ws[(k4 + 2) * 64 + j0];
            float4 w3 = *(const float4*)&ws[(k4 + 3) * 64 + j0];
            float tr[4][4] = {{t0.x, t0.y, t0.z, t0.w}, {t1.x, t1.y, t1.z, t1.w},
                              {t2.x, t2.y, t2.z, t2.w}, {t3.x, t3.y, t3.z, t3.w}};
            float wr[4][4] = {{w0.x, w0.y, w0.z, w0.w}, {w1v.x, w1v.y, w1v.z, w1v.w},
                              {w2v.x, w2v.y, w2v.z, w2v.w}, {w3.x, w3.y, w3.z, w3.w}};
#pragma unroll
            for (int kk = 0; kk < 4; ++kk)
#pragma unroll
                for (int i = 0; i < 4; ++i)
#pragma unroll
                    for (int j = 0; j < 4; ++j)
                        a2[i][j] += tr[i][kk] * wr[kk][j];
        }
        int col = cc * 64 + j0;
        float4 bb = __ldg((const float4*)&b2[col]);
#pragma unroll
        for (int i = 0; i < 4; ++i) {
            int row = rowBase + r0 + i;
            if (row < n) {
                float4 o;
                o.x = a2[i][0] + bb.x;
                o.y = a2[i][1] + bb.y;
                o.z = a2[i][2] + bb.z;
                o.w = a2[i][3] + bb.w;
                *(float4*)&Y[(long)row * LD_OUT + col] = o;
            }
        }
    }
}

// ---------------------------------------------------------------------------
// CSR gather-max aggregation: aggr[node] = max over in-edges of h[src]; 0 if none.
// ---------------------------------------------------------------------------
template<int C>
__global__ void __launch_bounds__(256) agg_kernel(
    float* __restrict__ Xn,
    const int* __restrict__ csr, const int* __restrict__ off, int n)
{
    constexpr int LD  = 2 * C;
    constexpr int V   = C / 4;
    constexpr int LPE = (V < 32) ? V : 32;
    constexpr int EPW = 32 / LPE;
    constexpr int NV  = V / LPE;

    int gwarp = (int)((blockIdx.x * 256u + threadIdx.x) >> 5);
    int lane  = threadIdx.x & 31;
    int node  = gwarp * EPW + (EPW > 1 ? lane / LPE : 0);
    if (node >= n) return;
    int li = lane % LPE;

    int beg = off[node], end = off[node + 1];

    float4 m[NV];
#pragma unroll
    for (int v = 0; v < NV; ++v)
        m[v] = make_float4(-INFINITY, -INFINITY, -INFINITY, -INFINITY);

    int e = beg;
    for (; e + 3 < end; e += 4) {
        int s0 = __ldg(csr + e), s1 = __ldg(csr + e + 1);
        int s2 = __ldg(csr + e + 2), s3 = __ldg(csr + e + 3);
        const float4* h0 = (const float4*)(Xn + (long)s0 * LD) + li;
        const float4* h1 = (const float4*)(Xn + (long)s1 * LD) + li;
        const float4* h2 = (const float4*)(Xn + (long)s2 * LD) + li;
        const float4* h3 = (const float4*)(Xn + (long)s3 * LD) + li;
#pragma unroll
        for (int v = 0; v < NV; ++v) {
            float4 a = h0[v * LPE];
            float4 b = h1[v * LPE];
            float4 c = h2[v * LPE];
            float4 d = h3[v * LPE];
            m[v] = max4(m[v], max4(max4(a, b), max4(c, d)));
        }
    }
    for (; e < end; ++e) {
        const float4* h0 = (const float4*)(Xn + (long)__ldg(csr + e) * LD) + li;
#pragma unroll
        for (int v = 0; v < NV; ++v)
            m[v] = max4(m[v], h0[v * LPE]);
    }

    float4* ap = (float4*)(Xn + (long)node * LD + C);
    if (beg == end) {
#pragma unroll
        for (int v = 0; v < NV; ++v)
            ap[li + v * LPE] = make_float4(0.f, 0.f, 0.f, 0.f);
    } else {
#pragma unroll
        for (int v = 0; v < NV; ++v)
            ap[li + v * LPE] = m[v];
    }
}

// ---------------------------------------------------------------------------
// Cluster max-pool via CSR
// ---------------------------------------------------------------------------
__global__ void __launch_bounds__(128) pool_kernel(
    const float* __restrict__ X3, const int* __restrict__ ccsr,
    const int* __restrict__ coff, float* __restrict__ pool)
{
    int c = blockIdx.x;
    int t = threadIdx.x;
    int beg = coff[c], end = coff[c + 1];

    float4 m = make_float4(-INFINITY, -INFINITY, -INFINITY, -INFINITY);
    int i = beg;
    for (; i + 3 < end; i += 4) {
        float4 a = ((const float4*)(X3 + (long)ccsr[i] * 512))[t];
        float4 b = ((const float4*)(X3 + (long)ccsr[i + 1] * 512))[t];
        float4 c2 = ((const float4*)(X3 + (long)ccsr[i + 2] * 512))[t];
        float4 d = ((const float4*)(X3 + (long)ccsr[i + 3] * 512))[t];
        m = max4(m, max4(max4(a, b), max4(c2, d)));
    }
    for (; i < end; ++i)
        m = max4(m, ((const float4*)(X3 + (long)ccsr[i] * 512))[t]);
    if (beg == end) m = make_float4(0.f, 0.f, 0.f, 0.f);
    ((float4*)(pool + (long)c * 512))[t] = m;
}

// Column-wise normalize, coalesced
__global__ void __launch_bounds__(256) normalize_kernel(
    const float* __restrict__ pool, float* __restrict__ out, int nc)
{
    int lane  = threadIdx.x & 31;
    int phase = threadIdx.x >> 5;
    int col   = blockIdx.x * 32 + lane;

    float ss = 0.f;
    for (int r = phase; r < nc; r += 8) {
        float v = pool[(long)r * 512 + col];
        ss += v * v;
    }
    __shared__ float red[256];
    red[threadIdx.x] = ss;
    __syncthreads();
#pragma unroll
    for (int s = 128; s >= 32; s >>= 1) {
        if (threadIdx.x < s) red[threadIdx.x] += red[threadIdx.x + s];
        __syncthreads();
    }
    if (threadIdx.x < 32) red[threadIdx.x] = 1.0f / (sqrtf(red[threadIdx.x]) + 1e-6f);
    __syncthreads();
    float inv = red[lane];
    for (int r = phase; r < nc; r += 8)
        out[(long)r * 512 + col] = pool[(long)r * 512 + col] * inv;
}

// ---------------------------------------------------------------------------
extern "C" void kernel_launch(void* const* d_in, const int* in_sizes, int n_in,
                              void* d_out, int out_size)
{
    const float* x   = (const float*)d_in[0];
    const int*   ei  = (const int*)d_in[1];
    const int*   cl  = (const int*)d_in[2];
    const float *w1_0 = (const float*)d_in[3],  *b1_0 = (const float*)d_in[4];
    const float *w2_0 = (const float*)d_in[5],  *b2_0 = (const float*)d_in[6];
    const float *w1_1 = (const float*)d_in[7],  *b1_1 = (const float*)d_in[8];
    const float *w2_1 = (const float*)d_in[9],  *b2_1 = (const float*)d_in[10];
    const float *w1_2 = (const float*)d_in[11], *b1_2 = (const float*)d_in[12];
    const float *w2_2 = (const float*)d_in[13], *b2_2 = (const float*)d_in[14];

    int n  = in_sizes[0] / 64;
    int E  = in_sizes[1] / 2;
    int nc = out_size / 512;
    const int* src = ei;
    const int* dst = ei + E;

    float* X1;   cudaGetSymbolAddress((void**)&X1, g_X1);
    float* X2;   cudaGetSymbolAddress((void**)&X2, g_X2);
    float* X3;   cudaGetSymbolAddress((void**)&X3, g_X3);
    float* pool; cudaGetSymbolAddress((void**)&pool, g_pool);
    float* tp;   cudaGetSymbolAddress((void**)&tp, g_tp);
    int *cnt, *off, *cur, *csr, *ccnt, *coff, *ccur, *ccsr;
    cudaGetSymbolAddress((void**)&cnt,  g_cnt);
    cudaGetSymbolAddress((void**)&off,  g_off);
    cudaGetSymbolAddress((void**)&cur,  g_cur);
    cudaGetSymbolAddress((void**)&csr,  g_csr);
    cudaGetSymbolAddress((void**)&ccnt, g_ccnt);
    cudaGetSymbolAddress((void**)&coff, g_coff);
    cudaGetSymbolAddress((void**)&ccur, g_ccur);
    cudaGetSymbolAddress((void**)&ccsr, g_ccsr);

    static cudaStream_t s2 = nullptr;
    static cudaEvent_t evFork = nullptr, evCsr = nullptr;
    static cudaEvent_t ev0 = nullptr, evH1 = nullptr, ev1 = nullptr, evH2 = nullptr;
    if (!s2) {
        cudaStreamCreateWithFlags(&s2, cudaStreamNonBlocking);
        cudaEventCreateWithFlags(&evFork, cudaEventDisableTiming);
        cudaEventCreateWithFlags(&evCsr,  cudaEventDisableTiming);
        cudaEventCreateWithFlags(&ev0,    cudaEventDisableTiming);
        cudaEventCreateWithFlags(&evH1,   cudaEventDisableTiming);
        cudaEventCreateWithFlags(&ev1,    cudaEventDisableTiming);
        cudaEventCreateWithFlags(&evH2,   cudaEventDisableTiming);
    }

    int nb = (n + 63) / 64;

    // ---- side stream: CSR build (overlaps mlp layer 0) ----
    cudaEventRecord(evFork, 0);
    cudaStreamWaitEvent(s2, evFork, 0);
    cudaMemsetAsync(cnt,  0, (size_t)n  * sizeof(int), s2);
    cudaMemsetAsync(ccnt, 0, (size_t)nc * sizeof(int), s2);
    hist_kernel<<<(E + 255) / 256, 256, 0, s2>>>(dst, cnt, E);
    hist_kernel<<<(n + 255) / 256, 256, 0, s2>>>(cl, ccnt, n);
    scan_kernel<<<1, 1024, 0, s2>>>(cnt, off, cur, n);
    scan_kernel<<<1, 1024, 0, s2>>>(ccnt, coff, ccur, nc);
    fill_edge_kernel<<<(E + 255) / 256, 256, 0, s2>>>(src, dst, cur, csr, E);
    fill_node_kernel<<<(n + 255) / 256, 256, 0, s2>>>(cl, ccur, ccsr, n);
    cudaEventRecord(evCsr, s2);

    // ---- Layer 0: 64 -> 64 (no concat, no head) ----
    mlp_tail<64, 64, 0, 64, false><<<nb, 256>>>(x, nullptr, w1_0, b1_0, w2_0, b2_0, X1, n);
    cudaEventRecord(ev0, 0);

    // side: head of layer 1 (reads X1 h-half only) overlaps agg0
    cudaStreamWaitEvent(s2, ev0, 0);
    mlp_head<128, 0, 64><<<nb, 256, 0, s2>>>(X1, w1_1, tp, n);
    cudaEventRecord(evH1, s2);

    cudaStreamWaitEvent(0, evCsr, 0);
    agg_kernel<64><<<((n + 1) / 2 * 32 + 255) / 256, 256>>>(X1, csr, off, n);

    // ---- Layer 1 tail: 128 -> 128 ----
    cudaStreamWaitEvent(0, evH1, 0);
    mlp_tail<128, 128, 64, 64, true><<<nb, 256>>>(X1, tp, w1_1, b1_1, w2_1, b2_1, X2, n);
    cudaEventRecord(ev1, 0);

    // side: head of layer 2 overlaps agg1
    cudaStreamWaitEvent(s2, ev1, 0);
    mlp_head<256, 0, 128><<<nb, 256, 0, s2>>>(X2, w1_2, tp, n);
    cudaEventRecord(evH2, s2);

    agg_kernel<128><<<(n * 32 + 255) / 256, 256>>>(X2, csr, off, n);

    // ---- Layer 2 tail: 256 -> 256 ----
    cudaStreamWaitEvent(0, evH2, 0);
    mlp_tail<256, 256, 128, 128, true><<<nb, 256>>>(X2, tp, w1_2, b1_2, w2_2, b2_2, X3, n);
    agg_kernel<256><<<(n * 32 + 255) / 256, 256>>>(X3, csr, off, n);

    // ---- Cluster pool + normalize ----
    pool_kernel<<<nc, 128>>>(X3, ccsr, coff, pool);
    normalize_kernel<<<16, 256>>>(pool, (float*)d_out, nc);
}

// round 10
// speedup vs baseline: 1.4087x; 1.2425x over previous
#include <cuda_runtime.h>
#include <cuda_bf16.h>
#include <cstdint>

// ---------------------------------------------------------------------------
// SubGraph: 3x (MLP -> gather/scatter-max -> concat) -> cluster max-pool ->
// column-wise L2 normalization.
// N=50000, E=800000, C0=64, H=64, NC=2500. Channels 64->128->256->512.
// Round 10 (= round 9 re-bench; infra flake): MLP on tensor cores via
// mma.sync.m16n8k16 bf16 with hi/lo split (3-term, ~1e-5 accuracy).
// CSR-gather agg + pool unchanged.
// ---------------------------------------------------------------------------

// Static scratch (no allocations allowed)
__device__ __align__(16) float g_X1[50000 * 128];
__device__ __align__(16) float g_X2[50000 * 256];
__device__ __align__(16) float g_X3[50000 * 512];
__device__ __align__(16) float g_pool[2500 * 512];

__device__ int g_cnt[50000];
__device__ int g_off[50001];
__device__ int g_cur[50000];
__device__ int g_csr[800000];

__device__ int g_ccnt[2500];
__device__ int g_coff[2501];
__device__ int g_ccur[2500];
__device__ int g_ccsr[50000];

__device__ __forceinline__ float4 max4(float4 a, float4 b) {
    return make_float4(fmaxf(a.x, b.x), fmaxf(a.y, b.y),
                       fmaxf(a.z, b.z), fmaxf(a.w, b.w));
}

// ---------------------------------------------------------------------------
// CSR build
// ---------------------------------------------------------------------------
__global__ void hist_kernel(const int* __restrict__ idx, int* __restrict__ cnt, int m)
{
    int i = blockIdx.x * blockDim.x + threadIdx.x;
    if (i < m) atomicAdd(&cnt[__ldg(idx + i)], 1);
}

__global__ void scan_kernel(const int* __restrict__ cnt, int* __restrict__ off,
                            int* __restrict__ cur, int n)
{
    __shared__ int sums[1024];
    int tid = threadIdx.x;
    int chunk = (n + 1023) >> 10;
    int start = tid * chunk;
    int lim = min(start + chunk, n);
    int s = 0;
    for (int i = start; i < lim; ++i) s += cnt[i];
    sums[tid] = s;
    __syncthreads();
    for (int d = 1; d < 1024; d <<= 1) {
        int v = (tid >= d) ? sums[tid - d] : 0;
        __syncthreads();
        sums[tid] += v;
        __syncthreads();
    }
    int run = (tid == 0) ? 0 : sums[tid - 1];
    for (int i = start; i < lim; ++i) {
        off[i] = run; cur[i] = run;
        run += cnt[i];
    }
    if (tid == 1023) off[n] = sums[1023];
}

__global__ void fill_edge_kernel(const int* __restrict__ src, const int* __restrict__ dst,
                                 int* __restrict__ cur, int* __restrict__ csr, int E)
{
    int e = blockIdx.x * blockDim.x + threadIdx.x;
    if (e >= E) return;
    int pos = atomicAdd(&cur[__ldg(dst + e)], 1);
    csr[pos] = __ldg(src + e);
}

__global__ void fill_node_kernel(const int* __restrict__ cl, int* __restrict__ ccur,
                                 int* __restrict__ ccsr, int n)
{
    int i = blockIdx.x * blockDim.x + threadIdx.x;
    if (i >= n) return;
    int pos = atomicAdd(&ccur[__ldg(cl + i)], 1);
    ccsr[pos] = i;
}

// ---------------------------------------------------------------------------
// bf16 split helpers + mma
// ---------------------------------------------------------------------------
__device__ __forceinline__ void split_pack(float x0, float x1, unsigned& hi, unsigned& lo)
{
    __nv_bfloat16 h0 = __float2bfloat16_rn(x0);
    __nv_bfloat16 h1 = __float2bfloat16_rn(x1);
    float f0 = __bfloat162float(h0), f1 = __bfloat162float(h1);
    __nv_bfloat16 l0 = __float2bfloat16_rn(x0 - f0);
    __nv_bfloat16 l1 = __float2bfloat16_rn(x1 - f1);
    hi = ((unsigned)__bfloat16_as_ushort(h1) << 16) | (unsigned)__bfloat16_as_ushort(h0);
    lo = ((unsigned)__bfloat16_as_ushort(l1) << 16) | (unsigned)__bfloat16_as_ushort(l0);
}

__device__ __forceinline__ void mma16816(float* c,
    unsigned a0, unsigned a1, unsigned a2, unsigned a3,
    unsigned b0, unsigned b1)
{
    asm volatile(
        "mma.sync.aligned.m16n8k16.row.col.f32.bf16.bf16.f32 "
        "{%0,%1,%2,%3}, {%4,%5,%6,%7}, {%8,%9}, {%0,%1,%2,%3};"
        : "+f"(c[0]), "+f"(c[1]), "+f"(c[2]), "+f"(c[3])
        : "r"(a0), "r"(a1), "r"(a2), "r"(a3), "r"(b0), "r"(b1));
}

// ---------------------------------------------------------------------------
// Tensor-core MLP: Y[:, :C] = relu(X[:, :C] @ w1 + b1) @ w2 + b2
// X: [n][C] (layer0: raw input; layers1/2: full concat row), Y stride 2C.
// Block: 256 thr = 8 warps (4 row x 2 col), tile 128 rows x 64 cols.
// Per warp 32x32 = 2 m16 x 4 n8 frags; K in 32-elem chunks; 3-term bf16 split.
// Smem (dynamic, words): A/t hi+lo 2*128*36, B hi+lo 2*64*36 = 55296 B.
// ---------------------------------------------------------------------------
template<int C>
__global__ void __launch_bounds__(256) mlp_mma_kernel(
    const float* __restrict__ X,
    const float* __restrict__ w1, const float* __restrict__ b1,
    const float* __restrict__ w2, const float* __restrict__ b2,
    float* __restrict__ Y, int n)
{
    constexpr int LD_OUT = 2 * C;
    constexpr int SA = 20;   // A chunk row stride (16 data words + 4 pad)
    constexpr int ST = 36;   // t row stride (32 data words + 4 pad)
    constexpr int SB = 36;   // B row stride (16 or 32 data words + pad)

    extern __shared__ unsigned smem[];
    unsigned* sA_hi = smem;                    // 128*36
    unsigned* sA_lo = sA_hi + 128 * ST;        // 128*36
    unsigned* sB_hi = sA_lo + 128 * ST;        // 64*36
    unsigned* sB_lo = sB_hi + 64 * SB;         // 64*36

    const int tid = threadIdx.x;
    const int wid = tid >> 5, lane = tid & 31;
    const int g = lane >> 2, t4 = lane & 3;
    const int warpRow = wid >> 1, warpCol = wid & 1;
    const int rowBase = blockIdx.x * 128;

    float c[2][4][4];
#pragma unroll
    for (int a = 0; a < 2; ++a)
#pragma unroll
        for (int b = 0; b < 4; ++b)
#pragma unroll
            for (int d = 0; d < 4; ++d) c[a][b][d] = 0.f;

    // ---- matmul1: t = X @ w1, K chunks of 32 ----
    for (int kc = 0; kc < C / 32; ++kc) {
        __syncthreads();
        // stage A chunk: 128 rows x 16 words (bf16x2), stride SA
#pragma unroll
        for (int it = 0; it < 8; ++it) {
            int idx = tid + it * 256;
            int r = idx >> 4, kw = idx & 15;
            int row = rowBase + r;
            float2 v = make_float2(0.f, 0.f);
            if (row < n) v = *(const float2*)&X[(long)row * C + kc * 32 + kw * 2];
            unsigned hi, lo; split_pack(v.x, v.y, hi, lo);
            sA_hi[r * SA + kw] = hi; sA_lo[r * SA + kw] = lo;
        }
        // stage B chunk: Wt[n][kw] from w1[k][n] (coalesced along n)
        {
            int nn = tid & 63, k0 = tid >> 6;
#pragma unroll
            for (int kw = k0; kw < 16; kw += 4) {
                int k = kc * 32 + kw * 2;
                float x0 = __ldg(&w1[(long)k * 64 + nn]);
                float x1 = __ldg(&w1[(long)(k + 1) * 64 + nn]);
                unsigned hi, lo; split_pack(x0, x1, hi, lo);
                sB_hi[nn * SB + kw] = hi; sB_lo[nn * SB + kw] = lo;
            }
        }
        __syncthreads();

#pragma unroll
        for (int ks = 0; ks < 2; ++ks) {
            int kw0 = ks * 8;
            unsigned ah[2][4], al[2][4];
#pragma unroll
            for (int mt = 0; mt < 2; ++mt) {
                int r0 = warpRow * 32 + mt * 16;
                ah[mt][0] = sA_hi[(r0 + g) * SA + kw0 + t4];
                ah[mt][1] = sA_hi[(r0 + g + 8) * SA + kw0 + t4];
                ah[mt][2] = sA_hi[(r0 + g) * SA + kw0 + 4 + t4];
                ah[mt][3] = sA_hi[(r0 + g + 8) * SA + kw0 + 4 + t4];
                al[mt][0] = sA_lo[(r0 + g) * SA + kw0 + t4];
                al[mt][1] = sA_lo[(r0 + g + 8) * SA + kw0 + t4];
                al[mt][2] = sA_lo[(r0 + g) * SA + kw0 + 4 + t4];
                al[mt][3] = sA_lo[(r0 + g + 8) * SA + kw0 + 4 + t4];
            }
#pragma unroll
            for (int nt = 0; nt < 4; ++nt) {
                int nb_ = warpCol * 32 + nt * 8;
                unsigned bh0 = sB_hi[(nb_ + g) * SB + kw0 + t4];
                unsigned bh1 = sB_hi[(nb_ + g) * SB + kw0 + 4 + t4];
                unsigned bl0 = sB_lo[(nb_ + g) * SB + kw0 + t4];
                unsigned bl1 = sB_lo[(nb_ + g) * SB + kw0 + 4 + t4];
#pragma unroll
                for (int mt = 0; mt < 2; ++mt) {
                    mma16816(c[mt][nt], ah[mt][0], ah[mt][1], ah[mt][2], ah[mt][3], bh0, bh1);
                    mma16816(c[mt][nt], ah[mt][0], ah[mt][1], ah[mt][2], ah[mt][3], bl0, bl1);
                    mma16816(c[mt][nt], al[mt][0], al[mt][1], al[mt][2], al[mt][3], bh0, bh1);
                }
            }
        }
    }

    __syncthreads();   // all A/B reads done; safe to overwrite as t

    // ---- bias + relu; repack t (bf16 hi/lo) into sA with stride ST ----
#pragma unroll
    for (int mt = 0; mt < 2; ++mt) {
#pragma unroll
        for (int nt = 0; nt < 4; ++nt) {
            int j = warpCol * 32 + nt * 8 + t4 * 2;
            float2 bb = *(const float2*)&b1[j];
            float v0 = fmaxf(c[mt][nt][0] + bb.x, 0.f);
            float v1 = fmaxf(c[mt][nt][1] + bb.y, 0.f);
            float v2 = fmaxf(c[mt][nt][2] + bb.x, 0.f);
            float v3 = fmaxf(c[mt][nt][3] + bb.y, 0.f);
            int r0 = warpRow * 32 + mt * 16 + g;
            int wc = warpCol * 16 + nt * 4 + t4;
            unsigned hi, lo;
            split_pack(v0, v1, hi, lo);
            sA_hi[r0 * ST + wc] = hi; sA_lo[r0 * ST + wc] = lo;
            split_pack(v2, v3, hi, lo);
            sA_hi[(r0 + 8) * ST + wc] = hi; sA_lo[(r0 + 8) * ST + wc] = lo;
        }
    }

    // ---- matmul2: Y = t @ w2 + b2, 64-col output slices ----
    for (int cc = 0; cc < C / 64; ++cc) {
        __syncthreads();
        // stage B2: Wt2[n][kw] from w2[k][cc*64+n], k = 0..63 (32 words)
        {
            int nn = tid & 63, k0 = tid >> 6;
#pragma unroll
            for (int kw = k0; kw < 32; kw += 4) {
                int k = kw * 2;
                float x0 = __ldg(&w2[(long)k * C + cc * 64 + nn]);
                float x1 = __ldg(&w2[(long)(k + 1) * C + cc * 64 + nn]);
                unsigned hi, lo; split_pack(x0, x1, hi, lo);
                sB_hi[nn * SB + kw] = hi; sB_lo[nn * SB + kw] = lo;
            }
        }
        __syncthreads();

        float c2[2][4][4];
#pragma unroll
        for (int a = 0; a < 2; ++a)
#pragma unroll
            for (int b = 0; b < 4; ++b)
#pragma unroll
                for (int d = 0; d < 4; ++d) c2[a][b][d] = 0.f;

#pragma unroll
        for (int ks = 0; ks < 4; ++ks) {
            int kw0 = ks * 8;
            unsigned ah[2][4], al[2][4];
#pragma unroll
            for (int mt = 0; mt < 2; ++mt) {
                int r0 = warpRow * 32 + mt * 16;
                ah[mt][0] = sA_hi[(r0 + g) * ST + kw0 + t4];
                ah[mt][1] = sA_hi[(r0 + g + 8) * ST + kw0 + t4];
                ah[mt][2] = sA_hi[(r0 + g) * ST + kw0 + 4 + t4];
                ah[mt][3] = sA_hi[(r0 + g + 8) * ST + kw0 + 4 + t4];
                al[mt][0] = sA_lo[(r0 + g) * ST + kw0 + t4];
                al[mt][1] = sA_lo[(r0 + g + 8) * ST + kw0 + t4];
                al[mt][2] = sA_lo[(r0 + g) * ST + kw0 + 4 + t4];
                al[mt][3] = sA_lo[(r0 + g + 8) * ST + kw0 + 4 + t4];
            }
#pragma unroll
            for (int nt = 0; nt < 4; ++nt) {
                int nb_ = warpCol * 32 + nt * 8;
                unsigned bh0 = sB_hi[(nb_ + g) * SB + kw0 + t4];
                unsigned bh1 = sB_hi[(nb_ + g) * SB + kw0 + 4 + t4];
                unsigned bl0 = sB_lo[(nb_ + g) * SB + kw0 + t4];
                unsigned bl1 = sB_lo[(nb_ + g) * SB + kw0 + 4 + t4];
#pragma unroll
                for (int mt = 0; mt < 2; ++mt) {
                    mma16816(c2[mt][nt], ah[mt][0], ah[mt][1], ah[mt][2], ah[mt][3], bh0, bh1);
                    mma16816(c2[mt][nt], ah[mt][0], ah[mt][1], ah[mt][2], ah[mt][3], bl0, bl1);
                    mma16816(c2[mt][nt], al[mt][0], al[mt][1], al[mt][2], al[mt][3], bh0, bh1);
                }
            }
        }

        // + b2, store f32 to Y
#pragma unroll
        for (int mt = 0; mt < 2; ++mt) {
#pragma unroll
            for (int nt = 0; nt < 4; ++nt) {
                int j = cc * 64 + warpCol * 32 + nt * 8 + t4 * 2;
                float2 bb = *(const float2*)&b2[j];
                int r0 = rowBase + warpRow * 32 + mt * 16 + g;
                if (r0 < n)
                    *(float2*)&Y[(long)r0 * LD_OUT + j] =
                        make_float2(c2[mt][nt][0] + bb.x, c2[mt][nt][1] + bb.y);
                if (r0 + 8 < n)
                    *(float2*)&Y[(long)(r0 + 8) * LD_OUT + j] =
                        make_float2(c2[mt][nt][2] + bb.x, c2[mt][nt][3] + bb.y);
            }
        }
    }
}

// ---------------------------------------------------------------------------
// CSR gather-max aggregation: aggr[node] = max over in-edges of h[src]; 0 if none.
// ---------------------------------------------------------------------------
template<int C>
__global__ void __launch_bounds__(256) agg_kernel(
    float* __restrict__ Xn,
    const int* __restrict__ csr, const int* __restrict__ off, int n)
{
    constexpr int LD  = 2 * C;
    constexpr int V   = C / 4;
    constexpr int LPE = (V < 32) ? V : 32;
    constexpr int EPW = 32 / LPE;
    constexpr int NV  = V / LPE;

    int gwarp = (int)((blockIdx.x * 256u + threadIdx.x) >> 5);
    int lane  = threadIdx.x & 31;
    int node  = gwarp * EPW + (EPW > 1 ? lane / LPE : 0);
    if (node >= n) return;
    int li = lane % LPE;

    int beg = off[node], end = off[node + 1];

    float4 m[NV];
#pragma unroll
    for (int v = 0; v < NV; ++v)
        m[v] = make_float4(-INFINITY, -INFINITY, -INFINITY, -INFINITY);

    int e = beg;
    for (; e + 3 < end; e += 4) {
        int s0 = __ldg(csr + e), s1 = __ldg(csr + e + 1);
        int s2 = __ldg(csr + e + 2), s3 = __ldg(csr + e + 3);
        const float4* h0 = (const float4*)(Xn + (long)s0 * LD) + li;
        const float4* h1 = (const float4*)(Xn + (long)s1 * LD) + li;
        const float4* h2 = (const float4*)(Xn + (long)s2 * LD) + li;
        const float4* h3 = (const float4*)(Xn + (long)s3 * LD) + li;
#pragma unroll
        for (int v = 0; v < NV; ++v) {
            float4 a = h0[v * LPE];
            float4 b = h1[v * LPE];
            float4 c = h2[v * LPE];
            float4 d = h3[v * LPE];
            m[v] = max4(m[v], max4(max4(a, b), max4(c, d)));
        }
    }
    for (; e < end; ++e) {
        const float4* h0 = (const float4*)(Xn + (long)__ldg(csr + e) * LD) + li;
#pragma unroll
        for (int v = 0; v < NV; ++v)
            m[v] = max4(m[v], h0[v * LPE]);
    }

    float4* ap = (float4*)(Xn + (long)node * LD + C);
    if (beg == end) {
#pragma unroll
        for (int v = 0; v < NV; ++v)
            ap[li + v * LPE] = make_float4(0.f, 0.f, 0.f, 0.f);
    } else {
#pragma unroll
        for (int v = 0; v < NV; ++v)
            ap[li + v * LPE] = m[v];
    }
}

// ---------------------------------------------------------------------------
// Cluster max-pool via CSR
// ---------------------------------------------------------------------------
__global__ void __launch_bounds__(128) pool_kernel(
    const float* __restrict__ X3, const int* __restrict__ ccsr,
    const int* __restrict__ coff, float* __restrict__ pool)
{
    int c = blockIdx.x;
    int t = threadIdx.x;
    int beg = coff[c], end = coff[c + 1];

    float4 m = make_float4(-INFINITY, -INFINITY, -INFINITY, -INFINITY);
    int i = beg;
    for (; i + 3 < end; i += 4) {
        float4 a = ((const float4*)(X3 + (long)ccsr[i] * 512))[t];
        float4 b = ((const float4*)(X3 + (long)ccsr[i + 1] * 512))[t];
        float4 c2 = ((const float4*)(X3 + (long)ccsr[i + 2] * 512))[t];
        float4 d = ((const float4*)(X3 + (long)ccsr[i + 3] * 512))[t];
        m = max4(m, max4(max4(a, b), max4(c2, d)));
    }
    for (; i < end; ++i)
        m = max4(m, ((const float4*)(X3 + (long)ccsr[i] * 512))[t]);
    if (beg == end) m = make_float4(0.f, 0.f, 0.f, 0.f);
    ((float4*)(pool + (long)c * 512))[t] = m;
}

// Column-wise normalize, coalesced
__global__ void __launch_bounds__(256) normalize_kernel(
    const float* __restrict__ pool, float* __restrict__ out, int nc)
{
    int lane  = threadIdx.x & 31;
    int phase = threadIdx.x >> 5;
    int col   = blockIdx.x * 32 + lane;

    float ss = 0.f;
    for (int r = phase; r < nc; r += 8) {
        float v = pool[(long)r * 512 + col];
        ss += v * v;
    }
    __shared__ float red[256];
    red[threadIdx.x] = ss;
    __syncthreads();
#pragma unroll
    for (int s = 128; s >= 32; s >>= 1) {
        if (threadIdx.x < s) red[threadIdx.x] += red[threadIdx.x + s];
        __syncthreads();
    }
    if (threadIdx.x < 32) red[threadIdx.x] = 1.0f / (sqrtf(red[threadIdx.x]) + 1e-6f);
    __syncthreads();
    float inv = red[lane];
    for (int r = phase; r < nc; r += 8)
        out[(long)r * 512 + col] = pool[(long)r * 512 + col] * inv;
}

// ---------------------------------------------------------------------------
static constexpr int MLP_SMEM_BYTES = (2 * 128 * 36 + 2 * 64 * 36) * 4;  // 55296

extern "C" void kernel_launch(void* const* d_in, const int* in_sizes, int n_in,
                              void* d_out, int out_size)
{
    const float* x   = (const float*)d_in[0];
    const int*   ei  = (const int*)d_in[1];
    const int*   cl  = (const int*)d_in[2];
    const float *w1_0 = (const float*)d_in[3],  *b1_0 = (const float*)d_in[4];
    const float *w2_0 = (const float*)d_in[5],  *b2_0 = (const float*)d_in[6];
    const float *w1_1 = (const float*)d_in[7],  *b1_1 = (const float*)d_in[8];
    const float *w2_1 = (const float*)d_in[9],  *b2_1 = (const float*)d_in[10];
    const float *w1_2 = (const float*)d_in[11], *b1_2 = (const float*)d_in[12];
    const float *w2_2 = (const float*)d_in[13], *b2_2 = (const float*)d_in[14];

    int n  = in_sizes[0] / 64;
    int E  = in_sizes[1] / 2;
    int nc = out_size / 512;
    const int* src = ei;
    const int* dst = ei + E;

    float* X1;   cudaGetSymbolAddress((void**)&X1, g_X1);
    float* X2;   cudaGetSymbolAddress((void**)&X2, g_X2);
    float* X3;   cudaGetSymbolAddress((void**)&X3, g_X3);
    float* pool; cudaGetSymbolAddress((void**)&pool, g_pool);
    int *cnt, *off, *cur, *csr, *ccnt, *coff, *ccur, *ccsr;
    cudaGetSymbolAddress((void**)&cnt,  g_cnt);
    cudaGetSymbolAddress((void**)&off,  g_off);
    cudaGetSymbolAddress((void**)&cur,  g_cur);
    cudaGetSymbolAddress((void**)&csr,  g_csr);
    cudaGetSymbolAddress((void**)&ccnt, g_ccnt);
    cudaGetSymbolAddress((void**)&coff, g_coff);
    cudaGetSymbolAddress((void**)&ccur, g_ccur);
    cudaGetSymbolAddress((void**)&ccsr, g_ccsr);

    cudaFuncSetAttribute(mlp_mma_kernel<64>,
                         cudaFuncAttributeMaxDynamicSharedMemorySize, MLP_SMEM_BYTES);
    cudaFuncSetAttribute(mlp_mma_kernel<128>,
                         cudaFuncAttributeMaxDynamicSharedMemorySize, MLP_SMEM_BYTES);
    cudaFuncSetAttribute(mlp_mma_kernel<256>,
                         cudaFuncAttributeMaxDynamicSharedMemorySize, MLP_SMEM_BYTES);

    // Round-4-proven topology: one side stream, two events.
    static cudaStream_t s2 = nullptr;
    static cudaEvent_t evFork = nullptr, evCsr = nullptr;
    if (!s2) {
        cudaStreamCreateWithFlags(&s2, cudaStreamNonBlocking);
        cudaEventCreateWithFlags(&evFork, cudaEventDisableTiming);
        cudaEventCreateWithFlags(&evCsr,  cudaEventDisableTiming);
    }

    // ---- CSR build on side stream (overlaps mlp layer 0) ----
    cudaEventRecord(evFork, 0);
    cudaStreamWaitEvent(s2, evFork, 0);
    cudaMemsetAsync(cnt,  0, (size_t)n  * sizeof(int), s2);
    cudaMemsetAsync(ccnt, 0, (size_t)nc * sizeof(int), s2);
    hist_kernel<<<(E + 255) / 256, 256, 0, s2>>>(dst, cnt, E);
    hist_kernel<<<(n + 255) / 256, 256, 0, s2>>>(cl, ccnt, n);
    scan_kernel<<<1, 1024, 0, s2>>>(cnt, off, cur, n);
    scan_kernel<<<1, 1024, 0, s2>>>(ccnt, coff, ccur, nc);
    fill_edge_kernel<<<(E + 255) / 256, 256, 0, s2>>>(src, dst, cur, csr, E);
    fill_node_kernel<<<(n + 255) / 256, 256, 0, s2>>>(cl, ccur, ccsr, n);
    cudaEventRecord(evCsr, s2);

    int nb = (n + 127) / 128;

    // ---- Layer 0: 64 -> 64 ----
    mlp_mma_kernel<64><<<nb, 256, MLP_SMEM_BYTES>>>(x, w1_0, b1_0, w2_0, b2_0, X1, n);
    cudaStreamWaitEvent(0, evCsr, 0);
    agg_kernel<64><<<((n + 1) / 2 * 32 + 255) / 256, 256>>>(X1, csr, off, n);

    // ---- Layer 1: 128 -> 128 ----
    mlp_mma_kernel<128><<<nb, 256, MLP_SMEM_BYTES>>>(X1, w1_1, b1_1, w2_1, b2_1, X2, n);
    agg_kernel<128><<<(n * 32 + 255) / 256, 256>>>(X2, csr, off, n);

    // ---- Layer 2: 256 -> 256 ----
    mlp_mma_kernel<256><<<nb, 256, MLP_SMEM_BYTES>>>(X2, w1_2, b1_2, w2_2, b2_2, X3, n);
    agg_kernel<256><<<(n * 32 + 255) / 256, 256>>>(X3, csr, off, n);

    // ---- Cluster pool + normalize ----
    pool_kernel<<<nc, 128>>>(X3, ccsr, coff, pool);
    normalize_kernel<<<16, 256>>>(pool, (float*)d_out, nc);
}